// round 1
// baseline (speedup 1.0000x reference)
#include <cuda_runtime.h>
#include <math.h>

// Problem constants
#define BATCH 4
#define SEQ   2048
#define DMODEL 1024
#define NHEAD 16
#define HDIM  64
#define MROWS (BATCH * SEQ)   // 8192

// Scratch (allocation-free rule: __device__ globals)
__device__ float g_Q[(size_t)MROWS * DMODEL];
__device__ float g_K[(size_t)MROWS * DMODEL];
__device__ float g_V[(size_t)MROWS * DMODEL];
__device__ float g_C[(size_t)MROWS * DMODEL];

// ---------------------------------------------------------------------------
// GEMM: C[M, N] = A[M, K] @ W[N, K]^T + bias[N]
// M = 8192, N = K = 1024 (compile-time). BM=BN=128, BK=16, 8x8 per thread.
// ---------------------------------------------------------------------------
__global__ __launch_bounds__(256) void gemm_bias_kernel(
    const float* __restrict__ A,
    const float* __restrict__ W,
    const float* __restrict__ bias,
    float* __restrict__ C)
{
    const int BM = 128, BN = 128, BK = 16;
    __shared__ float As[BK][BM];   // k-major
    __shared__ float Ws[BK][BN];   // k-major

    const int tid = threadIdx.x;
    const int tx = tid & 15;       // 0..15 -> N direction
    const int ty = tid >> 4;       // 0..15 -> M direction
    const int m0 = blockIdx.y * BM;
    const int n0 = blockIdx.x * BN;

    float acc[8][8];
    #pragma unroll
    for (int i = 0; i < 8; i++)
        #pragma unroll
        for (int j = 0; j < 8; j++)
            acc[i][j] = 0.0f;

    for (int k0 = 0; k0 < DMODEL; k0 += BK) {
        // Load A tile (128 rows x 16 cols) transposed into As[k][m]
        #pragma unroll
        for (int t = tid; t < BM * (BK / 4); t += 256) {
            int r  = t >> 2;        // 0..127
            int c4 = t & 3;         // 0..3
            float4 v = *(const float4*)(A + (size_t)(m0 + r) * DMODEL + k0 + c4 * 4);
            As[c4 * 4 + 0][r] = v.x;
            As[c4 * 4 + 1][r] = v.y;
            As[c4 * 4 + 2][r] = v.z;
            As[c4 * 4 + 3][r] = v.w;
        }
        // Load W tile (128 rows x 16 cols) transposed into Ws[k][n]
        #pragma unroll
        for (int t = tid; t < BN * (BK / 4); t += 256) {
            int r  = t >> 2;
            int c4 = t & 3;
            float4 v = *(const float4*)(W + (size_t)(n0 + r) * DMODEL + k0 + c4 * 4);
            Ws[c4 * 4 + 0][r] = v.x;
            Ws[c4 * 4 + 1][r] = v.y;
            Ws[c4 * 4 + 2][r] = v.z;
            Ws[c4 * 4 + 3][r] = v.w;
        }
        __syncthreads();

        #pragma unroll
        for (int k = 0; k < BK; k++) {
            float ra[8], rb[8];
            *(float4*)(ra + 0) = *(const float4*)&As[k][ty * 8 + 0];
            *(float4*)(ra + 4) = *(const float4*)&As[k][ty * 8 + 4];
            *(float4*)(rb + 0) = *(const float4*)&Ws[k][tx * 8 + 0];
            *(float4*)(rb + 4) = *(const float4*)&Ws[k][tx * 8 + 4];
            #pragma unroll
            for (int i = 0; i < 8; i++)
                #pragma unroll
                for (int j = 0; j < 8; j++)
                    acc[i][j] = fmaf(ra[i], rb[j], acc[i][j]);
        }
        __syncthreads();
    }

    // Epilogue with bias
    float bb[8];
    #pragma unroll
    for (int j = 0; j < 8; j++) bb[j] = bias[n0 + tx * 8 + j];

    #pragma unroll
    for (int i = 0; i < 8; i++) {
        size_t row = (size_t)(m0 + ty * 8 + i);
        #pragma unroll
        for (int j4 = 0; j4 < 8; j4 += 4) {
            float4 r;
            r.x = acc[i][j4 + 0] + bb[j4 + 0];
            r.y = acc[i][j4 + 1] + bb[j4 + 1];
            r.z = acc[i][j4 + 2] + bb[j4 + 2];
            r.w = acc[i][j4 + 3] + bb[j4 + 3];
            *(float4*)(C + row * DMODEL + n0 + tx * 8 + j4) = r;
        }
    }
}

// ---------------------------------------------------------------------------
// Causal flash attention, fp32. Br = Bc = 64, DK = 64.
// grid = (SEQ/64, BATCH*NHEAD), block = 256 threads (16x16, 4x4 tile each).
// Dynamic smem: Qs[64][64] (k-major), Ks[64][64] (k-major),
//               Vs[64][64] (natural),  Ps[64][64] (j-major) = 64 KB.
// ---------------------------------------------------------------------------
__global__ __launch_bounds__(256) void attn_kernel(
    const float* __restrict__ Q,
    const float* __restrict__ K,
    const float* __restrict__ V,
    float* __restrict__ Cx)
{
    extern __shared__ float sm[];
    float (*Qs)[64] = (float(*)[64])(sm);           // Qs[dk][m]
    float (*Ks)[64] = (float(*)[64])(sm + 4096);    // Ks[dk][n]
    float (*Vs)[64] = (float(*)[64])(sm + 8192);    // Vs[j][nd]
    float (*Ps)[64] = (float(*)[64])(sm + 12288);   // Ps[j][m]

    const int tid = threadIdx.x;
    const int tx = tid & 15;     // key / head-dim direction
    const int ty = tid >> 4;     // query direction
    const int qt = blockIdx.x;
    const int bh = blockIdx.y;
    const int b  = bh >> 4;
    const int h  = bh & 15;
    const int q0 = qt * 64;

    const size_t base = ((size_t)b * SEQ) * DMODEL + (size_t)h * HDIM;

    // Load Q tile, transposed -> Qs[dk][m]
    for (int t = tid; t < 64 * 16; t += 256) {
        int r  = t >> 4;     // query row in tile
        int c4 = t & 15;     // head-dim float4 index
        float4 v = *(const float4*)(Q + base + (size_t)(q0 + r) * DMODEL + c4 * 4);
        Qs[c4 * 4 + 0][r] = v.x;
        Qs[c4 * 4 + 1][r] = v.y;
        Qs[c4 * 4 + 2][r] = v.z;
        Qs[c4 * 4 + 3][r] = v.w;
    }

    float o[4][4];
    float mi[4], li[4];
    #pragma unroll
    for (int i = 0; i < 4; i++) {
        mi[i] = -1e30f;
        li[i] = 0.0f;
        #pragma unroll
        for (int j = 0; j < 4; j++) o[i][j] = 0.0f;
    }

    const float scale = 0.125f;   // 1/sqrt(64)

    for (int kt = 0; kt <= qt; kt++) {
        const int k0 = kt * 64;
        __syncthreads();   // previous iteration fully consumed Ks/Vs/Ps

        // Load K tile transposed -> Ks[dk][n]; V tile natural -> Vs[j][nd]
        for (int t = tid; t < 64 * 16; t += 256) {
            int r  = t >> 4;
            int c4 = t & 15;
            const float* kp = K + base + (size_t)(k0 + r) * DMODEL + c4 * 4;
            float4 kv = *(const float4*)kp;
            Ks[c4 * 4 + 0][r] = kv.x;
            Ks[c4 * 4 + 1][r] = kv.y;
            Ks[c4 * 4 + 2][r] = kv.z;
            Ks[c4 * 4 + 3][r] = kv.w;
            float4 vv = *(const float4*)(V + base + (size_t)(k0 + r) * DMODEL + c4 * 4);
            *(float4*)&Vs[r][c4 * 4] = vv;
        }
        __syncthreads();

        // S = (Q @ K^T) * scale  (4x4 per thread)
        float s[4][4];
        #pragma unroll
        for (int i = 0; i < 4; i++)
            #pragma unroll
            for (int j = 0; j < 4; j++) s[i][j] = 0.0f;

        #pragma unroll 8
        for (int dk = 0; dk < 64; dk++) {
            float4 qa = *(const float4*)&Qs[dk][ty * 4];
            float4 kb = *(const float4*)&Ks[dk][tx * 4];
            float qr[4] = {qa.x, qa.y, qa.z, qa.w};
            float kr[4] = {kb.x, kb.y, kb.z, kb.w};
            #pragma unroll
            for (int i = 0; i < 4; i++)
                #pragma unroll
                for (int j = 0; j < 4; j++)
                    s[i][j] = fmaf(qr[i], kr[j], s[i][j]);
        }

        #pragma unroll
        for (int i = 0; i < 4; i++)
            #pragma unroll
            for (int j = 0; j < 4; j++) s[i][j] *= scale;

        // Causal mask on the diagonal tile
        if (kt == qt) {
            #pragma unroll
            for (int i = 0; i < 4; i++) {
                int qg = ty * 4 + i;
                #pragma unroll
                for (int j = 0; j < 4; j++) {
                    int kg = tx * 4 + j;
                    if (kg > qg) s[i][j] = -1e9f;
                }
            }
        }

        // Online softmax update
        float mnew[4], rowsum[4], alpha[4];
        #pragma unroll
        for (int i = 0; i < 4; i++) {
            float mx = fmaxf(fmaxf(s[i][0], s[i][1]), fmaxf(s[i][2], s[i][3]));
            #pragma unroll
            for (int off = 8; off >= 1; off >>= 1)
                mx = fmaxf(mx, __shfl_xor_sync(0xffffffffu, mx, off, 16));
            mnew[i] = fmaxf(mi[i], mx);
        }
        #pragma unroll
        for (int i = 0; i < 4; i++) {
            float rs = 0.0f;
            #pragma unroll
            for (int j = 0; j < 4; j++) {
                s[i][j] = __expf(s[i][j] - mnew[i]);
                rs += s[i][j];
            }
            #pragma unroll
            for (int off = 8; off >= 1; off >>= 1)
                rs += __shfl_xor_sync(0xffffffffu, rs, off, 16);
            rowsum[i] = rs;
            alpha[i] = __expf(mi[i] - mnew[i]);
            li[i] = li[i] * alpha[i] + rowsum[i];
            mi[i] = mnew[i];
            #pragma unroll
            for (int j = 0; j < 4; j++) o[i][j] *= alpha[i];
        }

        // Write P transposed -> Ps[j][m]
        #pragma unroll
        for (int i = 0; i < 4; i++)
            #pragma unroll
            for (int j = 0; j < 4; j++)
                Ps[tx * 4 + j][ty * 4 + i] = s[i][j];
        __syncthreads();

        // O += P @ V
        #pragma unroll 8
        for (int j = 0; j < 64; j++) {
            float4 pa = *(const float4*)&Ps[j][ty * 4];
            float4 vb = *(const float4*)&Vs[j][tx * 4];
            float pr[4] = {pa.x, pa.y, pa.z, pa.w};
            float vr[4] = {vb.x, vb.y, vb.z, vb.w};
            #pragma unroll
            for (int i = 0; i < 4; i++)
                #pragma unroll
                for (int jj = 0; jj < 4; jj++)
                    o[i][jj] = fmaf(pr[i], vr[jj], o[i][jj]);
        }
    }

    // Epilogue: normalize and store
    #pragma unroll
    for (int i = 0; i < 4; i++) {
        float inv = 1.0f / li[i];
        float4 r;
        r.x = o[i][0] * inv;
        r.y = o[i][1] * inv;
        r.z = o[i][2] * inv;
        r.w = o[i][3] * inv;
        *(float4*)(Cx + base + (size_t)(q0 + ty * 4 + i) * DMODEL + tx * 4) = r;
    }
}

// ---------------------------------------------------------------------------
extern "C" void kernel_launch(void* const* d_in, const int* in_sizes, int n_in,
                              void* d_out, int out_size)
{
    const float* query = (const float*)d_in[0];
    const float* key   = (const float*)d_in[1];
    const float* value = (const float*)d_in[2];
    // d_in[3] = mask: constant lower-triangular causal mask; handled analytically.
    const float* wq = (const float*)d_in[4];
    const float* bq = (const float*)d_in[5];
    const float* wk = (const float*)d_in[6];
    const float* bk = (const float*)d_in[7];
    const float* wv = (const float*)d_in[8];
    const float* bv = (const float*)d_in[9];
    const float* wo = (const float*)d_in[10];
    const float* bo = (const float*)d_in[11];
    float* out = (float*)d_out;

    float *Q, *K, *V, *C;
    cudaGetSymbolAddress((void**)&Q, g_Q);
    cudaGetSymbolAddress((void**)&K, g_K);
    cudaGetSymbolAddress((void**)&V, g_V);
    cudaGetSymbolAddress((void**)&C, g_C);

    cudaFuncSetAttribute(attn_kernel,
                         cudaFuncAttributeMaxDynamicSharedMemorySize, 64 * 1024);

    dim3 gridG(DMODEL / 128, MROWS / 128);   // (8, 64)
    gemm_bias_kernel<<<gridG, 256>>>(query, wq, bq, Q);
    gemm_bias_kernel<<<gridG, 256>>>(key,   wk, bk, K);
    gemm_bias_kernel<<<gridG, 256>>>(value, wv, bv, V);

    dim3 gridA(SEQ / 64, BATCH * NHEAD);     // (32, 64)
    attn_kernel<<<gridA, 256, 64 * 1024>>>(Q, K, V, C);

    gemm_bias_kernel<<<gridG, 256>>>(C, wo, bo, out);
}

// round 4
// speedup vs baseline: 3.1577x; 3.1577x over previous
#include <cuda_runtime.h>
#include <cstdint>
#include <math.h>

// Problem constants
#define BATCH 4
#define SEQ   2048
#define DMODEL 1024
#define NHEAD 16
#define HDIM  64
#define MROWS (BATCH * SEQ)   // 8192

// Scratch (allocation-free rule: __device__ globals)
__device__ float g_Q[(size_t)MROWS * DMODEL];
__device__ float g_K[(size_t)MROWS * DMODEL];
__device__ float g_V[(size_t)MROWS * DMODEL];
__device__ float g_C[(size_t)MROWS * DMODEL];

// ---------------------------------------------------------------------------
// Helpers: tf32 convert (round-to-nearest) and m16n8k8 tf32 MMA
// ---------------------------------------------------------------------------
__device__ __forceinline__ uint32_t f2tf(float x) {
    uint32_t r;
    asm("cvt.rna.tf32.f32 %0, %1;" : "=r"(r) : "f"(x));
    return r;
}
__device__ __forceinline__ void mma_tf32(float* c, const uint32_t* a, const uint32_t* b) {
    asm volatile(
        "mma.sync.aligned.m16n8k8.row.col.f32.tf32.tf32.f32 "
        "{%0,%1,%2,%3}, {%4,%5,%6,%7}, {%8,%9}, {%0,%1,%2,%3};"
        : "+f"(c[0]), "+f"(c[1]), "+f"(c[2]), "+f"(c[3])
        : "r"(a[0]), "r"(a[1]), "r"(a[2]), "r"(a[3]), "r"(b[0]), "r"(b[1]));
}

// ---------------------------------------------------------------------------
// GEMM: C[M,N] = A[M,K] @ W[N,K]^T + bias[N], via tf32 mma.sync.
// M=8192, N=K=1024. CTA tile 128x128, BK=32, 8 warps (4m x 2n), warp 32x64.
// Double-buffered smem, tf32 conversion fused into the smem store.
// grid = (8, 64), block = 256.
// ---------------------------------------------------------------------------
#define GSTR 36                 // smem row stride in floats (32 + 4 pad)
#define GTILE (128 * GSTR)      // u32s per tile buffer
#define GEMM_SMEM (4 * GTILE * 4)   // 2 matrices x 2 buffers = 73,728 B

__global__ __launch_bounds__(256, 2) void gemm_mma(
    const float* __restrict__ A,
    const float* __restrict__ W,
    const float* __restrict__ bias,
    float* __restrict__ C)
{
    extern __shared__ uint32_t smg[];
    uint32_t* As = smg;                 // [2][GTILE]
    uint32_t* Ws = smg + 2 * GTILE;     // [2][GTILE]

    const int tid  = threadIdx.x;
    const int lane = tid & 31;
    const int wid  = tid >> 5;
    const int wm   = wid & 3;           // warp m index (0..3)
    const int wn   = wid >> 2;          // warp n index (0..1)
    const int g    = lane >> 2;         // 0..7
    const int q    = lane & 3;          // 0..3
    const int m0 = blockIdx.y * 128;
    const int n0 = blockIdx.x * 128;

    float acc[2][8][4];
    #pragma unroll
    for (int mf = 0; mf < 2; mf++)
        #pragma unroll
        for (int nf = 0; nf < 8; nf++)
            #pragma unroll
            for (int j = 0; j < 4; j++)
                acc[mf][nf][j] = 0.0f;

    // Per-thread load slots: 4 float4 per matrix per chunk
    // idx = tid + i*256: row = idx>>3 (0..127), c4 = idx&7 (float4 within 32 cols)
    float4 av[4], wv[4];

    // ---- load chunk 0 ----
    #pragma unroll
    for (int i = 0; i < 4; i++) {
        int idx = tid + i * 256;
        int r = idx >> 3, c4 = idx & 7;
        av[i] = *(const float4*)(A + (size_t)(m0 + r) * DMODEL + c4 * 4);
        wv[i] = *(const float4*)(W + (size_t)(n0 + r) * DMODEL + c4 * 4);
    }
    #pragma unroll
    for (int i = 0; i < 4; i++) {
        int idx = tid + i * 256;
        int r = idx >> 3, c4 = idx & 7;
        uint4 ta = make_uint4(f2tf(av[i].x), f2tf(av[i].y), f2tf(av[i].z), f2tf(av[i].w));
        uint4 tw = make_uint4(f2tf(wv[i].x), f2tf(wv[i].y), f2tf(wv[i].z), f2tf(wv[i].w));
        *(uint4*)&As[r * GSTR + c4 * 4] = ta;
        *(uint4*)&Ws[r * GSTR + c4 * 4] = tw;
    }
    __syncthreads();

    const int NCHUNK = DMODEL / 32;   // 32
    for (int c = 0; c < NCHUNK; c++) {
        // prefetch next chunk into registers
        if (c + 1 < NCHUNK) {
            int k0 = (c + 1) * 32;
            #pragma unroll
            for (int i = 0; i < 4; i++) {
                int idx = tid + i * 256;
                int r = idx >> 3, c4 = idx & 7;
                av[i] = *(const float4*)(A + (size_t)(m0 + r) * DMODEL + k0 + c4 * 4);
                wv[i] = *(const float4*)(W + (size_t)(n0 + r) * DMODEL + k0 + c4 * 4);
            }
        }

        // compute on current buffer
        const uint32_t* Ab = As + (c & 1) * GTILE;
        const uint32_t* Wb = Ws + (c & 1) * GTILE;
        #pragma unroll
        for (int ks = 0; ks < 4; ks++) {
            int k = ks * 8;
            uint32_t af[2][4];
            #pragma unroll
            for (int mf = 0; mf < 2; mf++) {
                int rb = wm * 32 + mf * 16;
                af[mf][0] = Ab[(rb + g) * GSTR + k + q];
                af[mf][1] = Ab[(rb + g + 8) * GSTR + k + q];
                af[mf][2] = Ab[(rb + g) * GSTR + k + q + 4];
                af[mf][3] = Ab[(rb + g + 8) * GSTR + k + q + 4];
            }
            #pragma unroll
            for (int nf = 0; nf < 8; nf++) {
                int cb = wn * 64 + nf * 8;
                uint32_t bf[2];
                bf[0] = Wb[(cb + g) * GSTR + k + q];
                bf[1] = Wb[(cb + g) * GSTR + k + q + 4];
                mma_tf32(acc[0][nf], af[0], bf);
                mma_tf32(acc[1][nf], af[1], bf);
            }
        }

        // store next chunk
        if (c + 1 < NCHUNK) {
            uint32_t* An = As + ((c + 1) & 1) * GTILE;
            uint32_t* Wn = Ws + ((c + 1) & 1) * GTILE;
            #pragma unroll
            for (int i = 0; i < 4; i++) {
                int idx = tid + i * 256;
                int r = idx >> 3, c4 = idx & 7;
                uint4 ta = make_uint4(f2tf(av[i].x), f2tf(av[i].y), f2tf(av[i].z), f2tf(av[i].w));
                uint4 tw = make_uint4(f2tf(wv[i].x), f2tf(wv[i].y), f2tf(wv[i].z), f2tf(wv[i].w));
                *(uint4*)&An[r * GSTR + c4 * 4] = ta;
                *(uint4*)&Wn[r * GSTR + c4 * 4] = tw;
            }
            __syncthreads();
        }
    }

    // Epilogue with bias
    #pragma unroll
    for (int mf = 0; mf < 2; mf++) {
        int row0 = m0 + wm * 32 + mf * 16 + g;
        #pragma unroll
        for (int nf = 0; nf < 8; nf++) {
            int col = n0 + wn * 64 + nf * 8 + 2 * q;
            float b0 = __ldg(bias + col);
            float b1 = __ldg(bias + col + 1);
            float2 v0 = make_float2(acc[mf][nf][0] + b0, acc[mf][nf][1] + b1);
            float2 v1 = make_float2(acc[mf][nf][2] + b0, acc[mf][nf][3] + b1);
            *(float2*)(C + (size_t)row0 * DMODEL + col) = v0;
            *(float2*)(C + (size_t)(row0 + 8) * DMODEL + col) = v1;
        }
    }
}

// ---------------------------------------------------------------------------
// Causal flash attention via tf32 mma.sync. Br = Bc = 64, DK = 64.
// Block = 128 threads (4 warps), each warp owns 16 query rows.
// smem: Qs/Ks [64][68] tf32, Vt [64][68] tf32 (transposed), Ps [64][68] tf32.
// grid = (SEQ/64, BATCH*NHEAD).
// ---------------------------------------------------------------------------
#define ASTR 68
#define ATILE (64 * ASTR)
#define ATTN_SMEM (4 * ATILE * 4)    // 69,632 B

__global__ __launch_bounds__(128) void attn_mma(
    const float* __restrict__ Q,
    const float* __restrict__ K,
    const float* __restrict__ V,
    float* __restrict__ Cx)
{
    extern __shared__ uint32_t sma[];
    uint32_t* Qs = sma;
    uint32_t* Ks = sma + ATILE;
    uint32_t* Vt = sma + 2 * ATILE;
    uint32_t* Ps = sma + 3 * ATILE;

    const int tid  = threadIdx.x;
    const int lane = tid & 31;
    const int w    = tid >> 5;       // warp 0..3 -> query rows [w*16, w*16+16)
    const int g    = lane >> 2;
    const int q    = lane & 3;
    const int qt   = blockIdx.x;
    const int bh   = blockIdx.y;
    const int b    = bh >> 4;
    const int h    = bh & 15;
    const int q0   = qt * 64;

    const size_t base = ((size_t)b * SEQ) * DMODEL + (size_t)h * HDIM;

    // Load Q tile (scaled by 1/sqrt(dk), tf32-rounded)
    #pragma unroll
    for (int i = 0; i < 8; i++) {
        int idx = tid + i * 128;
        int r = idx >> 4, c4 = idx & 15;
        float4 v = *(const float4*)(Q + base + (size_t)(q0 + r) * DMODEL + c4 * 4);
        uint4 t = make_uint4(f2tf(v.x * 0.125f), f2tf(v.y * 0.125f),
                             f2tf(v.z * 0.125f), f2tf(v.w * 0.125f));
        *(uint4*)&Qs[r * ASTR + c4 * 4] = t;
    }

    float o[8][4];
    #pragma unroll
    for (int nf = 0; nf < 8; nf++)
        #pragma unroll
        for (int j = 0; j < 4; j++) o[nf][j] = 0.0f;
    float mi0 = -1e30f, mi1 = -1e30f, li0 = 0.0f, li1 = 0.0f;

    for (int kt = 0; kt <= qt; kt++) {
        const int k0 = kt * 64;
        __syncthreads();   // previous iteration fully consumed Ks/Vt/Ps; Qs visible

        // Load K tile (natural [key][dk]) and V tile transposed -> Vt[dk][key]
        #pragma unroll
        for (int i = 0; i < 8; i++) {
            int idx = tid + i * 128;
            int r = idx >> 4, c4 = idx & 15;
            float4 kv = *(const float4*)(K + base + (size_t)(k0 + r) * DMODEL + c4 * 4);
            uint4 tk = make_uint4(f2tf(kv.x), f2tf(kv.y), f2tf(kv.z), f2tf(kv.w));
            *(uint4*)&Ks[r * ASTR + c4 * 4] = tk;
            float4 vv = *(const float4*)(V + base + (size_t)(k0 + r) * DMODEL + c4 * 4);
            Vt[(c4 * 4 + 0) * ASTR + r] = f2tf(vv.x);
            Vt[(c4 * 4 + 1) * ASTR + r] = f2tf(vv.y);
            Vt[(c4 * 4 + 2) * ASTR + r] = f2tf(vv.z);
            Vt[(c4 * 4 + 3) * ASTR + r] = f2tf(vv.w);
        }
        __syncthreads();

        // S = Q @ K^T (warp: 16 rows x 64 keys)
        float s[8][4];
        #pragma unroll
        for (int nf = 0; nf < 8; nf++)
            #pragma unroll
            for (int j = 0; j < 4; j++) s[nf][j] = 0.0f;

        #pragma unroll
        for (int ks = 0; ks < 8; ks++) {
            int k = ks * 8;
            int rb = w * 16;
            uint32_t af[4];
            af[0] = Qs[(rb + g) * ASTR + k + q];
            af[1] = Qs[(rb + g + 8) * ASTR + k + q];
            af[2] = Qs[(rb + g) * ASTR + k + q + 4];
            af[3] = Qs[(rb + g + 8) * ASTR + k + q + 4];
            #pragma unroll
            for (int nf = 0; nf < 8; nf++) {
                uint32_t bf[2];
                bf[0] = Ks[(nf * 8 + g) * ASTR + k + q];
                bf[1] = Ks[(nf * 8 + g) * ASTR + k + q + 4];
                mma_tf32(s[nf], af, bf);
            }
        }

        // Causal mask on the diagonal tile
        if (kt == qt) {
            int row0 = q0 + w * 16 + g;
            int row1 = row0 + 8;
            #pragma unroll
            for (int nf = 0; nf < 8; nf++) {
                int c0 = k0 + nf * 8 + 2 * q;
                if (c0 > row0)     s[nf][0] = -1e30f;
                if (c0 + 1 > row0) s[nf][1] = -1e30f;
                if (c0 > row1)     s[nf][2] = -1e30f;
                if (c0 + 1 > row1) s[nf][3] = -1e30f;
            }
        }

        // Online softmax (rows g and g+8 owned by this lane's quad)
        float mx0 = -1e30f, mx1 = -1e30f;
        #pragma unroll
        for (int nf = 0; nf < 8; nf++) {
            mx0 = fmaxf(mx0, fmaxf(s[nf][0], s[nf][1]));
            mx1 = fmaxf(mx1, fmaxf(s[nf][2], s[nf][3]));
        }
        mx0 = fmaxf(mx0, __shfl_xor_sync(0xffffffffu, mx0, 1));
        mx0 = fmaxf(mx0, __shfl_xor_sync(0xffffffffu, mx0, 2));
        mx1 = fmaxf(mx1, __shfl_xor_sync(0xffffffffu, mx1, 1));
        mx1 = fmaxf(mx1, __shfl_xor_sync(0xffffffffu, mx1, 2));
        float mn0 = fmaxf(mi0, mx0);
        float mn1 = fmaxf(mi1, mx1);

        float rs0 = 0.0f, rs1 = 0.0f;
        #pragma unroll
        for (int nf = 0; nf < 8; nf++) {
            s[nf][0] = __expf(s[nf][0] - mn0);
            s[nf][1] = __expf(s[nf][1] - mn0);
            s[nf][2] = __expf(s[nf][2] - mn1);
            s[nf][3] = __expf(s[nf][3] - mn1);
            rs0 += s[nf][0] + s[nf][1];
            rs1 += s[nf][2] + s[nf][3];
        }
        rs0 += __shfl_xor_sync(0xffffffffu, rs0, 1);
        rs0 += __shfl_xor_sync(0xffffffffu, rs0, 2);
        rs1 += __shfl_xor_sync(0xffffffffu, rs1, 1);
        rs1 += __shfl_xor_sync(0xffffffffu, rs1, 2);

        float al0 = __expf(mi0 - mn0);
        float al1 = __expf(mi1 - mn1);
        li0 = li0 * al0 + rs0;
        li1 = li1 * al1 + rs1;
        mi0 = mn0;
        mi1 = mn1;
        #pragma unroll
        for (int nf = 0; nf < 8; nf++) {
            o[nf][0] *= al0;
            o[nf][1] *= al0;
            o[nf][2] *= al1;
            o[nf][3] *= al1;
        }

        // P -> smem (tf32), own 16 rows only
        #pragma unroll
        for (int nf = 0; nf < 8; nf++) {
            int r0 = w * 16 + g;
            int cc = nf * 8 + 2 * q;
            Ps[r0 * ASTR + cc]       = f2tf(s[nf][0]);
            Ps[r0 * ASTR + cc + 1]   = f2tf(s[nf][1]);
            Ps[(r0 + 8) * ASTR + cc]     = f2tf(s[nf][2]);
            Ps[(r0 + 8) * ASTR + cc + 1] = f2tf(s[nf][3]);
        }
        __syncwarp();

        // O += P @ V   (A = Ps rows, B = Vt[dk][key] col-major in key)
        #pragma unroll
        for (int ks = 0; ks < 8; ks++) {
            int k = ks * 8;
            int rb = w * 16;
            uint32_t af[4];
            af[0] = Ps[(rb + g) * ASTR + k + q];
            af[1] = Ps[(rb + g + 8) * ASTR + k + q];
            af[2] = Ps[(rb + g) * ASTR + k + q + 4];
            af[3] = Ps[(rb + g + 8) * ASTR + k + q + 4];
            #pragma unroll
            for (int nf = 0; nf < 8; nf++) {
                uint32_t bf[2];
                bf[0] = Vt[(nf * 8 + g) * ASTR + k + q];
                bf[1] = Vt[(nf * 8 + g) * ASTR + k + q + 4];
                mma_tf32(o[nf], af, bf);
            }
        }
    }

    // Epilogue: normalize and store
    float inv0 = 1.0f / li0;
    float inv1 = 1.0f / li1;
    int row0 = q0 + w * 16 + g;
    #pragma unroll
    for (int nf = 0; nf < 8; nf++) {
        int col = nf * 8 + 2 * q;
        float2 v0 = make_float2(o[nf][0] * inv0, o[nf][1] * inv0);
        float2 v1 = make_float2(o[nf][2] * inv1, o[nf][3] * inv1);
        *(float2*)(Cx + base + (size_t)row0 * DMODEL + col) = v0;
        *(float2*)(Cx + base + (size_t)(row0 + 8) * DMODEL + col) = v1;
    }
}

// ---------------------------------------------------------------------------
extern "C" void kernel_launch(void* const* d_in, const int* in_sizes, int n_in,
                              void* d_out, int out_size)
{
    const float* query = (const float*)d_in[0];
    const float* key   = (const float*)d_in[1];
    const float* value = (const float*)d_in[2];
    // d_in[3] = mask: constant causal tril; handled analytically.
    const float* wq = (const float*)d_in[4];
    const float* bq = (const float*)d_in[5];
    const float* wk = (const float*)d_in[6];
    const float* bk = (const float*)d_in[7];
    const float* wv = (const float*)d_in[8];
    const float* bv = (const float*)d_in[9];
    const float* wo = (const float*)d_in[10];
    const float* bo = (const float*)d_in[11];
    float* out = (float*)d_out;

    float *Q, *K, *V, *C;
    cudaGetSymbolAddress((void**)&Q, g_Q);
    cudaGetSymbolAddress((void**)&K, g_K);
    cudaGetSymbolAddress((void**)&V, g_V);
    cudaGetSymbolAddress((void**)&C, g_C);

    cudaFuncSetAttribute(gemm_mma,
                         cudaFuncAttributeMaxDynamicSharedMemorySize, GEMM_SMEM);
    cudaFuncSetAttribute(attn_mma,
                         cudaFuncAttributeMaxDynamicSharedMemorySize, ATTN_SMEM);

    dim3 gridG(DMODEL / 128, MROWS / 128);   // (8, 64)
    gemm_mma<<<gridG, 256, GEMM_SMEM>>>(query, wq, bq, Q);
    gemm_mma<<<gridG, 256, GEMM_SMEM>>>(key,   wk, bk, K);
    gemm_mma<<<gridG, 256, GEMM_SMEM>>>(value, wv, bv, V);

    dim3 gridA(SEQ / 64, BATCH * NHEAD);     // (32, 64)
    attn_mma<<<gridA, 128, ATTN_SMEM>>>(Q, K, V, C);

    gemm_mma<<<gridG, 256, GEMM_SMEM>>>(C, wo, bo, out);
}